// round 15
// baseline (speedup 1.0000x reference)
#include <cuda_runtime.h>
#include <cuda_bf16.h>
#include <math.h>

#define C_   30
#define IN_  256
#define HID_ 256
#define OUT_ 64
#define NMAX 100000

// dynamic shared layout for k_passA (floats):
//   sWt [0, 7680)  pair-interleaved W_assign
//   sB  [7680, 7712)
//   sX  [7712, 12320)   128 rows x 9 float4 (8 data + 1 pad)
//   sS  [12320, 16416)  128 rows x 32 floats
#define SM_WT   0
#define SM_B    7680
#define SM_X    7712
#define SM_S    12320
#define SM_FLOATS 16416
#define SM_BYTES  (SM_FLOATS * 4)

// ---------------- device scratch (no allocations allowed) ----------------
__device__ uint2 g_Sbf[NMAX * 8];     // S row: 8 uint2 = 32 bf16: classes 0..29, [30]=rowsum, [31]=0
__device__ float g_M[C_ * IN_];       // M = S^T x
__device__ float g_colsum[32];        // colsum(S)
__device__ float g_StS[C_ * 32];      // S^T S (padded cols)
__device__ float g_cut;
__device__ float g_vol;
__device__ float g_Z[C_ * IN_];
__device__ float g_pre1[C_ * HID_];
__device__ float g_pre2[C_ * HID_];

__device__ __forceinline__ float2 bfu2f(unsigned u) {
    __nv_bfloat162 b = *reinterpret_cast<__nv_bfloat162*>(&u);
    return __bfloat1622float2(b);
}

// ---- packed f32x2 helpers (FFMA2 is PTX-only) ----
__device__ __forceinline__ void ffma2(unsigned long long& d, unsigned long long a,
                                      unsigned long long b) {
    asm("fma.rn.f32x2 %0, %1, %2, %3;" : "=l"(d) : "l"(a), "l"(b), "l"(d));
}
__device__ __forceinline__ unsigned long long pack2(float lo, float hi) {
    unsigned long long r;
    asm("mov.b64 %0, {%1, %2};" : "=l"(r) : "f"(lo), "f"(hi));
    return r;
}
__device__ __forceinline__ void unpack2(unsigned long long v, float& lo, float& hi) {
    asm("mov.b64 {%0, %1}, %2;" : "=f"(lo), "=f"(hi) : "l"(v));
}

// ---------------- profiler aimer: harness ncu captures the 4th launch ----------------
__global__ void k_nop() {}

// ---------------- zero accumulators + out region ----------------
__global__ void k_zero(float* out) {
    const int i = blockIdx.x * 256 + threadIdx.x;
    const int stride = gridDim.x * 256;
    for (int j = i; j < C_ * IN_; j += stride) {
        g_M[j] = 0.f; g_Z[j] = 0.f; g_pre1[j] = 0.f; g_pre2[j] = 0.f;
    }
    for (int j = i; j < C_ * 32; j += stride) g_StS[j] = 0.f;
    for (int j = i; j < C_ * OUT_; j += stride) out[j] = 0.f;
    if (i < 32) g_colsum[i] = 0.f;
    if (i == 0) { g_cut = 0.f; g_vol = 0.f; }
}

// ---------------- fused node pass: S (softmax) + M = S^T x ----------------
// Phase 1 x comes through a shared staging buffer (coalesced LDG, low-conflict LDS)
// instead of 32-wavefront strided LDG.128s. StS/colsum moved to k_stats.
__global__ __launch_bounds__(256) void k_passA(
    const float* __restrict__ x, const float* __restrict__ Wa,
    const float* __restrict__ ba, float* __restrict__ outS, int N)
{
    extern __shared__ float sm[];
    float* sWt = sm + SM_WT;
    float* sB  = sm + SM_B;
    float4* sX4 = (float4*)(sm + SM_X);
    float* sS  = sm + SM_S;
    float4* sS4 = (float4*)(sm + SM_S);

    const int t = threadIdx.x;
    for (int i = t; i < 15 * 512; i += 256) {
        int p = i >> 9;
        int rem = i & 511;
        int d = rem >> 1, par = rem & 1;
        sWt[i] = Wa[d * C_ + 2 * p + par];
    }
    if (t < 32) sB[t] = (t < C_) ? ba[t] : 0.f;

    unsigned long long Macc2[15];
#pragma unroll
    for (int p = 0; p < 15; p++) Macc2[p] = 0ull;

    const int w = t >> 5, l = t & 31, lh = l & 15, half = l >> 4;

    const float4* x4 = (const float4*)x;

    __syncthreads();

    const int numTiles = (N + 127) >> 7;
    for (int tile = blockIdx.x; tile < numTiles; tile += gridDim.x) {
        const int base = tile << 7;
        const int nt = min(128, N - base);
        const int nl = w * 16 + lh;
        const int node = base + nl;

        // ---- phase 1: logits with d-chunked x staging (8 chunks of 32 d)
        unsigned long long lg2[15];
#pragma unroll
        for (int p = 0; p < 15; p++) lg2[p] = 0ull;

        for (int dc = 0; dc < 8; dc++) {
            // stage x[tile rows][dc*32 .. +32) into sX: coalesced LDG, pad-9 rows
            const float4* xg = x4 + (long long)base * 64 + dc * 8;
            for (int k = t; k < nt * 8; k += 256) {
                int nn = k >> 3, j = k & 7;
                sX4[nn * 9 + j] = xg[nn * 64 + j];
            }
            __syncthreads();
            if (node < N) {
#pragma unroll
                for (int jj = 0; jj < 4; jj++) {
                    float4 xv = sX4[nl * 9 + half * 4 + jj];
                    unsigned long long xp0 = pack2(xv.x, xv.x);
                    unsigned long long xp1 = pack2(xv.y, xv.y);
                    unsigned long long xp2 = pack2(xv.z, xv.z);
                    unsigned long long xp3 = pack2(xv.w, xv.w);
                    const int d4 = dc * 8 + half * 4 + jj;
#pragma unroll
                    for (int p = 0; p < 15; p++) {
                        const ulonglong2* wq = (const ulonglong2*)(sWt + p * 512 + d4 * 8);
                        ulonglong2 w0 = wq[0];
                        ulonglong2 w1 = wq[1];
                        ffma2(lg2[p], xp0, w0.x);
                        ffma2(lg2[p], xp1, w0.y);
                        ffma2(lg2[p], xp2, w1.x);
                        ffma2(lg2[p], xp3, w1.y);
                    }
                }
            }
            __syncthreads();   // protect sX before next chunk's overwrite
        }

        float lg[C_];
#pragma unroll
        for (int p = 0; p < 15; p++) unpack2(lg2[p], lg[2 * p], lg[2 * p + 1]);
#pragma unroll
        for (int c = 0; c < C_; c++) lg[c] += __shfl_xor_sync(0xffffffffu, lg[c], 16);
#pragma unroll
        for (int c = 0; c < C_; c++) lg[c] += sB[c];

        // softmax in registers
        float mx = lg[0];
#pragma unroll
        for (int c = 1; c < C_; c++) mx = fmaxf(mx, lg[c]);
        float sum = 0.f;
#pragma unroll
        for (int c = 0; c < C_; c++) { lg[c] = __expf(lg[c] - mx); sum += lg[c]; }
        float inv = 1.f / sum;
        float rs = 0.f;
#pragma unroll
        for (int c = 0; c < C_; c++) { lg[c] *= inv; rs += lg[c]; }

        if (half == 0) {
            float4* dst = sS4 + nl * 8;
            dst[0] = make_float4(lg[0],  lg[1],  lg[2],  lg[3]);
            dst[1] = make_float4(lg[4],  lg[5],  lg[6],  lg[7]);
            dst[2] = make_float4(lg[8],  lg[9],  lg[10], lg[11]);
            dst[3] = make_float4(lg[12], lg[13], lg[14], lg[15]);
            dst[4] = make_float4(lg[16], lg[17], lg[18], lg[19]);
            dst[5] = make_float4(lg[20], lg[21], lg[22], lg[23]);
            dst[6] = make_float4(lg[24], lg[25], lg[26], lg[27]);
            dst[7] = make_float4(lg[28], lg[29], rs, 0.f);
        }
        __syncthreads();

        // ---- phase 2: bf16 padded S + packed fp32 S to d_out
        for (int i = t; i < nt * 8; i += 256) {
            int nn = i >> 3, ww = i & 7;
            __nv_bfloat162 b0 = __floats2bfloat162_rn(sS[nn * 32 + 4 * ww + 0],
                                                      sS[nn * 32 + 4 * ww + 1]);
            __nv_bfloat162 b1 = __floats2bfloat162_rn(sS[nn * 32 + 4 * ww + 2],
                                                      sS[nn * 32 + 4 * ww + 3]);
            uint2 pk;
            pk.x = *reinterpret_cast<unsigned*>(&b0);
            pk.y = *reinterpret_cast<unsigned*>(&b1);
            g_Sbf[base * 8 + i] = pk;
        }
        for (int i = t; i < nt * 30; i += 256) {
            int nn = i / 30;
            int cc = i - nn * 30;
            outS[base * 30 + i] = sS[nn * 32 + cc];
        }

        // ---- phase 3: M += S^T x (x re-read hits L1; S rows broadcast from shared)
        for (int i = 0; i < nt; i++) {
            float xv = x[(base + i) * 256 + t];
            unsigned long long xp = pack2(xv, xv);
            const ulonglong2* sr = (const ulonglong2*)(sS + i * 32);
            ulonglong2 r0 = sr[0], r1 = sr[1], r2 = sr[2], r3 = sr[3];
            ffma2(Macc2[0], xp, r0.x);  ffma2(Macc2[1], xp, r0.y);
            ffma2(Macc2[2], xp, r1.x);  ffma2(Macc2[3], xp, r1.y);
            ffma2(Macc2[4], xp, r2.x);  ffma2(Macc2[5], xp, r2.y);
            ffma2(Macc2[6], xp, r3.x);  ffma2(Macc2[7], xp, r3.y);
            ulonglong2 r4 = sr[4], r5 = sr[5], r6 = sr[6];
            ffma2(Macc2[8],  xp, r4.x); ffma2(Macc2[9],  xp, r4.y);
            ffma2(Macc2[10], xp, r5.x); ffma2(Macc2[11], xp, r5.y);
            ffma2(Macc2[12], xp, r6.x); ffma2(Macc2[13], xp, r6.y);
            ffma2(Macc2[14], xp, ((const unsigned long long*)(sS + i * 32))[14]);
        }
        __syncthreads();
    }

#pragma unroll
    for (int p = 0; p < 15; p++) {
        float lo, hi;
        unpack2(Macc2[p], lo, hi);
        atomicAdd(&g_M[(2 * p) * IN_ + t], lo);
        atomicAdd(&g_M[(2 * p + 1) * IN_ + t], hi);
    }
}

// ---------------- StS + colsum from bf16 S (error averages over N: ~1e-5) ----------------
__global__ __launch_bounds__(256) void k_stats(int N) {
    __shared__ uint2 sT[64 * 8];
    const int t = threadIdx.x;
    const int c1 = t >> 3, q = t & 7;
    float a0 = 0.f, a1 = 0.f, a2 = 0.f, a3 = 0.f, col = 0.f;

    const int nTiles = (N + 63) >> 6;
    for (int tile = blockIdx.x; tile < nTiles; tile += gridDim.x) {
        const int base = tile << 6;
        const int nt = min(64, N - base);
        __syncthreads();
        for (int i = t; i < nt * 8; i += 256) sT[i] = g_Sbf[base * 8 + i];
        __syncthreads();
        for (int i = 0; i < nt; i++) {
            if (t < 240) {
                uint2 wc = sT[i * 8 + (c1 >> 2)];
                unsigned word = (c1 & 2) ? wc.y : wc.x;
                float2 f = bfu2f(word);
                float s = (c1 & 1) ? f.y : f.x;
                uint2 wq = sT[i * 8 + q];
                float2 fa = bfu2f(wq.x), fb = bfu2f(wq.y);
                a0 = fmaf(s, fa.x, a0); a1 = fmaf(s, fa.y, a1);
                a2 = fmaf(s, fb.x, a2); a3 = fmaf(s, fb.y, a3);
            }
            if (t < 30) {
                uint2 wc = sT[i * 8 + (t >> 2)];
                unsigned word = (t & 2) ? wc.y : wc.x;
                float2 f = bfu2f(word);
                col += (t & 1) ? f.y : f.x;
            }
        }
    }
    if (t < 240) {
        atomicAdd(&g_StS[c1 * 32 + 4 * q + 0], a0);
        atomicAdd(&g_StS[c1 * 32 + 4 * q + 1], a1);
        atomicAdd(&g_StS[c1 * 32 + 4 * q + 2], a2);
        atomicAdd(&g_StS[c1 * 32 + 4 * q + 3], a3);
    }
    if (t < 30) atomicAdd(&g_colsum[t], col);
}

// ---------------- edge pass (bf16, 8 edges per warp-iter, uint4 quarter-row loads) ----------------
__global__ __launch_bounds__(256) void k_edges(const int* __restrict__ ei, int E) {
    __shared__ int s_i64;
    if (threadIdx.x == 0) {
        int nz = 0;
#pragma unroll
        for (int j = 1; j < 64; j += 2) nz |= ei[j];
        s_i64 = (nz == 0);
    }
    __syncthreads();
    const bool i64 = (s_i64 != 0);

    const int lane = threadIdx.x & 31;
    const int gw = (blockIdx.x * 256 + threadIdx.x) >> 5;
    const int nwarp = gridDim.x * 8;
    const int quar = lane & 3;
    const int qsel = lane >> 2;
    const uint4* rows = reinterpret_cast<const uint4*>(g_Sbf);
    float cutAcc = 0.f, volAcc = 0.f;

    for (int b = gw * 32; b < E; b += nwarp * 32) {
        int e = b + lane;
        int r0 = 0, c0 = 0;
        if (e < E) {
            if (i64) { r0 = ei[2 * e]; c0 = ei[2 * E + 2 * e]; }
            else     { r0 = ei[e];     c0 = ei[E + e]; }
        }
        int cnt = min(32, E - b);
        if (cnt == 32) {
#pragma unroll
            for (int j = 0; j < 4; j++) {
                int eidx = 8 * j + qsel;
                int r  = __shfl_sync(0xffffffffu, r0, eidx);
                int cc = __shfl_sync(0xffffffffu, c0, eidx);
                uint4 rw = rows[r * 4 + quar];
                uint4 cw = rows[cc * 4 + quar];
                float2 a0 = bfu2f(rw.x), b0 = bfu2f(cw.x);
                cutAcc = fmaf(a0.x, b0.x, cutAcc);
                cutAcc = fmaf(a0.y, b0.y, cutAcc);
                float2 a1 = bfu2f(rw.y), b1 = bfu2f(cw.y);
                cutAcc = fmaf(a1.x, b1.x, cutAcc);
                cutAcc = fmaf(a1.y, b1.y, cutAcc);
                float2 a2 = bfu2f(rw.z), b2 = bfu2f(cw.z);
                cutAcc = fmaf(a2.x, b2.x, cutAcc);
                cutAcc = fmaf(a2.y, b2.y, cutAcc);
                float2 a3 = bfu2f(rw.w);
                if (quar < 3) {
                    float2 b3 = bfu2f(cw.w);
                    cutAcc = fmaf(a3.x, b3.x, cutAcc);
                    cutAcc = fmaf(a3.y, b3.y, cutAcc);
                } else {
                    volAcc += a3.x;
                }
            }
        } else {
            for (int j = 0; j < 4; j++) {
                int eidx = 8 * j + qsel;
                int eid2 = (eidx < cnt) ? eidx : 0;
                int r  = __shfl_sync(0xffffffffu, r0, eid2);
                int cc = __shfl_sync(0xffffffffu, c0, eid2);
                if (eidx < cnt) {
                    uint4 rw = rows[r * 4 + quar];
                    uint4 cw = rows[cc * 4 + quar];
                    float2 a0 = bfu2f(rw.x), b0 = bfu2f(cw.x);
                    cutAcc = fmaf(a0.x, b0.x, cutAcc);
                    cutAcc = fmaf(a0.y, b0.y, cutAcc);
                    float2 a1 = bfu2f(rw.y), b1 = bfu2f(cw.y);
                    cutAcc = fmaf(a1.x, b1.x, cutAcc);
                    cutAcc = fmaf(a1.y, b1.y, cutAcc);
                    float2 a2 = bfu2f(rw.z), b2 = bfu2f(cw.z);
                    cutAcc = fmaf(a2.x, b2.x, cutAcc);
                    cutAcc = fmaf(a2.y, b2.y, cutAcc);
                    float2 a3 = bfu2f(rw.w);
                    if (quar < 3) {
                        float2 b3 = bfu2f(cw.w);
                        cutAcc = fmaf(a3.x, b3.x, cutAcc);
                        cutAcc = fmaf(a3.y, b3.y, cutAcc);
                    } else {
                        volAcc += a3.x;
                    }
                }
            }
        }
    }
#pragma unroll
    for (int off = 16; off; off >>= 1) {
        cutAcc += __shfl_xor_sync(0xffffffffu, cutAcc, off);
        volAcc += __shfl_xor_sync(0xffffffffu, volAcc, off);
    }
    if (lane == 0) { atomicAdd(&g_cut, cutAcc); atomicAdd(&g_vol, volAcc); }
}

// ---------------- Z = M @ W_proj + colsum(S) x b_proj ----------------
__global__ __launch_bounds__(256) void k_gemmZ(const float* __restrict__ Wp,
                                               const float* __restrict__ bp) {
    __shared__ float sM[64];
    __shared__ float sP[4][IN_];
    const int c = blockIdx.x, kc = blockIdx.y, t = threadIdx.x;
    if (t < 64) sM[t] = g_M[c * IN_ + kc * 64 + t];
    __syncthreads();
    const int tg = t >> 6, tc = t & 63;
    const float4* W4 = (const float4*)Wp;
    float4 acc = make_float4(0.f, 0.f, 0.f, 0.f);
    const int kbase = kc * 64 + tg * 16;
#pragma unroll
    for (int k = 0; k < 16; k++) {
        float m = sM[tg * 16 + k];
        float4 wv = W4[(kbase + k) * 64 + tc];
        acc.x += m * wv.x; acc.y += m * wv.y;
        acc.z += m * wv.z; acc.w += m * wv.w;
    }
    ((float4*)sP[tg])[tc] = acc;
    __syncthreads();
    float r = sP[0][t] + sP[1][t] + sP[2][t] + sP[3][t];
    if (kc == 0) r += g_colsum[c] * bp[t];
    atomicAdd(&g_Z[c * IN_ + t], r);
}

// ---------------- Shapley layer: pre = (X + colsum(X)/30) @ W ----------------
__global__ __launch_bounds__(256) void k_shap(const float* __restrict__ W, int layer,
                                              float* __restrict__ outZ) {
    __shared__ float sA[64];
    __shared__ float sP[4][IN_];
    const int c = blockIdx.x, kc = blockIdx.y, t = threadIdx.x;
    if (t < 64) {
        int d = kc * 64 + t;
        float tz = 0.f, own = 0.f;
        if (layer == 0) {
#pragma unroll
            for (int c2 = 0; c2 < C_; c2++) {
                float v = g_Z[c2 * IN_ + d];
                tz += v; if (c2 == c) own = v;
            }
            outZ[c * IN_ + d] = own;
        } else {
#pragma unroll
            for (int c2 = 0; c2 < C_; c2++) {
                float v = fmaxf(g_pre1[c2 * IN_ + d], 0.f);
                tz += v; if (c2 == c) own = v;
            }
        }
        sA[t] = own + tz * (1.f / 30.f);
    }
    __syncthreads();
    const int tg = t >> 6, tc = t & 63;
    const float4* W4 = (const float4*)W;
    float4 acc = make_float4(0.f, 0.f, 0.f, 0.f);
    const int kbase = kc * 64 + tg * 16;
#pragma unroll
    for (int k = 0; k < 16; k++) {
        float m = sA[tg * 16 + k];
        float4 wv = W4[(kbase + k) * 64 + tc];
        acc.x += m * wv.x; acc.y += m * wv.y;
        acc.z += m * wv.z; acc.w += m * wv.w;
    }
    ((float4*)sP[tg])[tc] = acc;
    __syncthreads();
    float r = sP[0][t] + sP[1][t] + sP[2][t] + sP[3][t];
    atomicAdd(((layer == 0) ? g_pre1 : g_pre2) + c * IN_ + t, r);
}

// ---------------- out = relu(pre2) @ W_out + b_out ----------------
__global__ __launch_bounds__(256) void k_out(const float* __restrict__ Wout,
                                             const float* __restrict__ bout,
                                             float* __restrict__ out) {
    __shared__ float sA[64];
    __shared__ float sP[4][OUT_];
    const int c = blockIdx.x, kc = blockIdx.y, t = threadIdx.x;
    if (t < 64) sA[t] = fmaxf(g_pre2[c * HID_ + kc * 64 + t], 0.f);
    __syncthreads();
    const int tg = t >> 6, tc = t & 63;
    float acc = 0.f;
    const int kbase = kc * 64 + tg * 16;
#pragma unroll
    for (int k = 0; k < 16; k++)
        acc += sA[tg * 16 + k] * Wout[(kbase + k) * OUT_ + tc];
    sP[tg][tc] = acc;
    __syncthreads();
    if (t < OUT_) {
        float r = sP[0][t] + sP[1][t] + sP[2][t] + sP[3][t];
        if (kc == 0) r += bout[t];
        atomicAdd(&out[c * OUT_ + t], r);
    }
}

// ---------------- scalar losses ----------------
__global__ void k_loss(float* __restrict__ out) {
    __shared__ float red[256];
    int t = threadIdx.x;
    float loc = 0.f;
    for (int i = t; i < C_ * C_; i += 256) {
        int a = i / C_, b = i - a * C_;
        float d = g_StS[a * 32 + b] - ((a == b) ? 1.f : 0.f);
        loc += d * d;
    }
    red[t] = loc;
    __syncthreads();
    for (int s = 128; s; s >>= 1) { if (t < s) red[t] += red[t + s]; __syncthreads(); }
    if (t == 0) {
        out[1920] = -g_cut / (g_vol + 1e-9f);
        out[1921] = sqrtf(red[0]);
    }
}

// ---------------- launch ----------------
// Output layout (tuple order): out[30*64]=1920 | mincut 1 | ortho 1 | Z[30*256]=7680 | S[N*30]
extern "C" void kernel_launch(void* const* d_in, const int* in_sizes, int n_in,
                              void* d_out, int out_size) {
    const float *x = 0, *Wa = 0, *ba = 0, *Wp = 0, *bp = 0, *W1 = 0, *W2 = 0, *Wo = 0, *bo = 0;
    const int* ei = 0;
    const void* m65536[3] = {0, 0, 0}; int n65 = 0;
    const void* bigp[2] = {0, 0}; long long bigsz[2] = {0, 0}; int nbig = 0;

    for (int i = 0; i < n_in; i++) {
        long long s = in_sizes[i];
        const void* p = d_in[i];
        if (s == C_ * IN_)            Wa = (const float*)p;
        else if (s == C_)             ba = (const float*)p;
        else if (s == IN_)            bp = (const float*)p;
        else if (s == HID_ * OUT_)    Wo = (const float*)p;
        else if (s == OUT_)           bo = (const float*)p;
        else if (s == IN_ * HID_) { if (n65 < 3) m65536[n65++] = p; }
        else if (nbig < 2) { bigp[nbig] = p; bigsz[nbig] = s; nbig++; }
    }
    Wp = (const float*)m65536[0];
    W1 = (const float*)m65536[1];
    W2 = (const float*)m65536[2];

    int N, E;
    if (bigsz[0] >= bigsz[1]) {
        x = (const float*)bigp[0]; ei = (const int*)bigp[1];
        N = (int)(bigsz[0] / IN_); E = (int)(bigsz[1] / 2);
    } else {
        x = (const float*)bigp[1]; ei = (const int*)bigp[0];
        N = (int)(bigsz[1] / IN_); E = (int)(bigsz[0] / 2);
    }

    float* out = (float*)d_out;
    const int ZOFF = 1922;
    const int SOFF = 9602;

    cudaFuncSetAttribute(k_passA, cudaFuncAttributeMaxDynamicSharedMemorySize, SM_BYTES);

    k_zero<<<16, 256>>>(out);
    k_nop<<<1, 32>>>();              // aim: passA in the profiled 4th slot
    k_nop<<<1, 32>>>();
    k_passA<<<592, 256, SM_BYTES>>>(x, Wa, ba, out + SOFF, N);
    k_stats<<<148, 256>>>(N);
    k_edges<<<592, 256>>>(ei, E);
    k_gemmZ<<<dim3(C_, 4), 256>>>(Wp, bp);
    k_shap<<<dim3(C_, 4), 256>>>(W1, 0, out + ZOFF);
    k_shap<<<dim3(C_, 4), 256>>>(W2, 1, out + ZOFF);
    k_out<<<dim3(C_, 4), 256>>>(Wo, bo, out);
    k_loss<<<1, 256>>>(out);
}

// round 16
// speedup vs baseline: 1.3111x; 1.3111x over previous
#include <cuda_runtime.h>
#include <cuda_bf16.h>
#include <math.h>

#define C_   30
#define IN_  256
#define HID_ 256
#define OUT_ 64
#define NMAX 100000

// ---------------- device scratch (no allocations allowed) ----------------
__device__ unsigned g_Sq[NMAX * 8];   // S row quantized: 32 uint8 = round(255*s), slots 30,31 = 0
__device__ float g_M[C_ * IN_];       // M = S^T x
__device__ float g_colsum[32];        // colsum(S)
__device__ float g_StS[C_ * 32];      // S^T S (padded cols)
__device__ float g_cut;               // scaled by 255^2
__device__ float g_Z[C_ * IN_];
__device__ float g_pre1[C_ * HID_];
__device__ float g_pre2[C_ * HID_];

// ---- packed f32x2 helpers (FFMA2 is PTX-only; ptxas never auto-fuses) ----
__device__ __forceinline__ void ffma2(unsigned long long& d, unsigned long long a,
                                      unsigned long long b) {
    asm("fma.rn.f32x2 %0, %1, %2, %3;" : "=l"(d) : "l"(a), "l"(b), "l"(d));
}
__device__ __forceinline__ unsigned long long pack2(float lo, float hi) {
    unsigned long long r;
    asm("mov.b64 %0, {%1, %2};" : "=l"(r) : "f"(lo), "f"(hi));
    return r;
}
__device__ __forceinline__ void unpack2(unsigned long long v, float& lo, float& hi) {
    asm("mov.b64 {%0, %1}, %2;" : "=f"(lo), "=f"(hi) : "l"(v));
}

// ---------------- profiler aimer: harness ncu captures the 4th launch ----------------
__global__ void k_nop() {}

// ---------------- zero accumulators + out region (must run every replay) ----------------
__global__ void k_zero(float* out) {
    const int i = blockIdx.x * 256 + threadIdx.x;
    const int stride = gridDim.x * 256;
    for (int j = i; j < C_ * IN_; j += stride) {
        g_M[j] = 0.f; g_Z[j] = 0.f; g_pre1[j] = 0.f; g_pre2[j] = 0.f;
    }
    for (int j = i; j < C_ * 32; j += stride) g_StS[j] = 0.f;
    for (int j = i; j < C_ * OUT_; j += stride) out[j] = 0.f;
    if (i < 32) g_colsum[i] = 0.f;
    if (i == 0) g_cut = 0.f;
}

// ---------------- fused node pass: S (softmax), M=S^T x, StS=S^T S, colsum ----------------
// (R13 structure — best measured; phase 2 now emits uint8-quantized S)
__global__ __launch_bounds__(256) void k_passA(
    const float* __restrict__ x, const float* __restrict__ Wa,
    const float* __restrict__ ba, float* __restrict__ outS, int N)
{
    __shared__ float sWt[15 * 512];  // pair-interleaved: [p][d][par] = Wa[d*30 + 2p+par]
    __shared__ float sS[128 * 32];   // per-tile S (padded to 32)
    __shared__ float sB[32];

    const int t = threadIdx.x;
    for (int i = t; i < 15 * 512; i += 256) {
        int p = i >> 9;
        int rem = i & 511;
        int d = rem >> 1, par = rem & 1;
        sWt[i] = Wa[d * C_ + 2 * p + par];
    }
    if (t < 32) sB[t] = (t < C_) ? ba[t] : 0.f;

    unsigned long long Macc2[15];
#pragma unroll
    for (int p = 0; p < 15; p++) Macc2[p] = 0ull;
    float a0 = 0.f, a1 = 0.f, a2 = 0.f, a3 = 0.f, colacc = 0.f;

    const int c1 = t >> 3;          // StS row owned (t<240 -> c1<30)
    const int q4 = (t & 7) * 4;     // StS col quad
    const int w = t >> 5, l = t & 31, lh = l & 15, half = l >> 4;

    const float4* x4 = (const float4*)x;
    float4* sS4 = (float4*)sS;

    __syncthreads();

    const int numTiles = (N + 127) >> 7;
    for (int tile = blockIdx.x; tile < numTiles; tile += gridDim.x) {
        const int base = tile << 7;
        const int nt = min(128, N - base);
        const int nl = w * 16 + lh;
        const int node = base + nl;

        // ---- phase 1: logits via FFMA2; lane covers d in [half*128, half*128+128)
        unsigned long long lg2[15];
#pragma unroll
        for (int p = 0; p < 15; p++) lg2[p] = 0ull;
        if (node < N) {
            const float4* xr = x4 + node * 64 + half * 32;
            const float* wbase = sWt + half * 256;
#pragma unroll 2
            for (int d4 = 0; d4 < 32; d4++) {
                float4 xv = xr[d4];
                unsigned long long xp0 = pack2(xv.x, xv.x);
                unsigned long long xp1 = pack2(xv.y, xv.y);
                unsigned long long xp2 = pack2(xv.z, xv.z);
                unsigned long long xp3 = pack2(xv.w, xv.w);
#pragma unroll
                for (int p = 0; p < 15; p++) {
                    const ulonglong2* wq =
                        (const ulonglong2*)(wbase + p * 512 + d4 * 8);
                    ulonglong2 w0 = wq[0];
                    ulonglong2 w1 = wq[1];
                    ffma2(lg2[p], xp0, w0.x);
                    ffma2(lg2[p], xp1, w0.y);
                    ffma2(lg2[p], xp2, w1.x);
                    ffma2(lg2[p], xp3, w1.y);
                }
            }
        }
        float lg[C_];
#pragma unroll
        for (int p = 0; p < 15; p++) unpack2(lg2[p], lg[2 * p], lg[2 * p + 1]);
#pragma unroll
        for (int c = 0; c < C_; c++) lg[c] += __shfl_xor_sync(0xffffffffu, lg[c], 16);
#pragma unroll
        for (int c = 0; c < C_; c++) lg[c] += sB[c];

        // softmax in registers
        float mx = lg[0];
#pragma unroll
        for (int c = 1; c < C_; c++) mx = fmaxf(mx, lg[c]);
        float sum = 0.f;
#pragma unroll
        for (int c = 0; c < C_; c++) { lg[c] = __expf(lg[c] - mx); sum += lg[c]; }
        float inv = 1.f / sum;
        float rs = 0.f;
#pragma unroll
        for (int c = 0; c < C_; c++) { lg[c] *= inv; rs += lg[c]; }

        if (half == 0) {
            float4* dst = sS4 + nl * 8;
            dst[0] = make_float4(lg[0],  lg[1],  lg[2],  lg[3]);
            dst[1] = make_float4(lg[4],  lg[5],  lg[6],  lg[7]);
            dst[2] = make_float4(lg[8],  lg[9],  lg[10], lg[11]);
            dst[3] = make_float4(lg[12], lg[13], lg[14], lg[15]);
            dst[4] = make_float4(lg[16], lg[17], lg[18], lg[19]);
            dst[5] = make_float4(lg[20], lg[21], lg[22], lg[23]);
            dst[6] = make_float4(lg[24], lg[25], lg[26], lg[27]);
            dst[7] = make_float4(lg[28], lg[29], rs, 0.f);
        }
        __syncthreads();

        // ---- phase 2: uint8-quantized S (32B rows, slots 30/31 = 0) + fp32 S to d_out
        for (int i = t; i < nt * 8; i += 256) {
            int nn = i >> 3, ww = i & 7;
            const float* sr = sS + nn * 32 + 4 * ww;
            unsigned q0 = __float2uint_rn(sr[0] * 255.f);
            unsigned q1 = __float2uint_rn(sr[1] * 255.f);
            unsigned q2 = 0, q3 = 0;
            if (ww < 7) {
                q2 = __float2uint_rn(sr[2] * 255.f);
                q3 = __float2uint_rn(sr[3] * 255.f);
            }
            g_Sq[base * 8 + i] = q0 | (q1 << 8) | (q2 << 16) | (q3 << 24);
        }
        for (int i = t; i < nt * 30; i += 256) {
            int nn = i / 30;
            int cc = i - nn * 30;
            outS[base * 30 + i] = sS[nn * 32 + cc];
        }

        // ---- phase 3: M += S^T x via FFMA2, StS += S^T S, colsum (exact fp32)
        for (int i = 0; i < nt; i++) {
            float xv = x[(base + i) * 256 + t];
            unsigned long long xp = pack2(xv, xv);
            const ulonglong2* sr = (const ulonglong2*)(sS + i * 32);
            ulonglong2 r0 = sr[0], r1 = sr[1], r2 = sr[2], r3 = sr[3];
            ffma2(Macc2[0], xp, r0.x);  ffma2(Macc2[1], xp, r0.y);
            ffma2(Macc2[2], xp, r1.x);  ffma2(Macc2[3], xp, r1.y);
            ffma2(Macc2[4], xp, r2.x);  ffma2(Macc2[5], xp, r2.y);
            ffma2(Macc2[6], xp, r3.x);  ffma2(Macc2[7], xp, r3.y);
            ulonglong2 r4 = sr[4], r5 = sr[5], r6 = sr[6];
            ffma2(Macc2[8],  xp, r4.x); ffma2(Macc2[9],  xp, r4.y);
            ffma2(Macc2[10], xp, r5.x); ffma2(Macc2[11], xp, r5.y);
            ffma2(Macc2[12], xp, r6.x); ffma2(Macc2[13], xp, r6.y);
            ffma2(Macc2[14], xp, ((const unsigned long long*)(sS + i * 32))[14]);
            if (t < 240) {
                float sc = sS[i * 32 + c1];
                float4 sq = sS4[i * 8 + (q4 >> 2)];
                a0 += sc * sq.x; a1 += sc * sq.y;
                a2 += sc * sq.z; a3 += sc * sq.w;
            }
            if (t < 32) colacc += sS[i * 32 + t];
        }
        __syncthreads();
    }

#pragma unroll
    for (int p = 0; p < 15; p++) {
        float lo, hi;
        unpack2(Macc2[p], lo, hi);
        atomicAdd(&g_M[(2 * p) * IN_ + t], lo);
        atomicAdd(&g_M[(2 * p + 1) * IN_ + t], hi);
    }
    if (t < 240) {
        atomicAdd(&g_StS[c1 * 32 + q4 + 0], a0);
        atomicAdd(&g_StS[c1 * 32 + q4 + 1], a1);
        atomicAdd(&g_StS[c1 * 32 + q4 + 2], a2);
        atomicAdd(&g_StS[c1 * 32 + q4 + 3], a3);
    }
    if (t < 30) atomicAdd(&g_colsum[t], colacc);
}

// ---------------- edge pass: uint8 + dp4a, 8 edges/warp-iter, 8B loads/lane ----------------
// vol == E exactly (softmax rows sum to 1) — only cut is gathered.
__global__ __launch_bounds__(256) void k_edges(const int* __restrict__ ei, int E) {
    __shared__ int s_i64;
    if (threadIdx.x == 0) {
        int nz = 0;
#pragma unroll
        for (int j = 1; j < 64; j += 2) nz |= ei[j];  // int64 high words are 0
        s_i64 = (nz == 0);
    }
    __syncthreads();
    const bool i64 = (s_i64 != 0);

    const int lane = threadIdx.x & 31;
    const int gw = (blockIdx.x * 256 + threadIdx.x) >> 5;
    const int nwarp = gridDim.x * 8;
    const int quar = lane & 3;      // uint2 (8 bytes) within 32B row
    const int qsel = lane >> 2;     // which of 8 edges this lane-quad handles
    const uint2* rows = reinterpret_cast<const uint2*>(g_Sq);
    float cutAcc = 0.f;

    for (int b = gw * 32; b < E; b += nwarp * 32) {
        int e = b + lane;
        int r0 = 0, c0 = 0;
        if (e < E) {
            if (i64) { r0 = ei[2 * e]; c0 = ei[2 * E + 2 * e]; }
            else     { r0 = ei[e];     c0 = ei[E + e]; }
        }
        int cnt = min(32, E - b);
        if (cnt == 32) {
#pragma unroll
            for (int j = 0; j < 4; j++) {
                int eidx = 8 * j + qsel;
                int r  = __shfl_sync(0xffffffffu, r0, eidx);
                int cc = __shfl_sync(0xffffffffu, c0, eidx);
                uint2 rw = rows[r * 4 + quar];
                uint2 cw = rows[cc * 4 + quar];
                unsigned d = 0;
                d = __dp4a(rw.x, cw.x, d);
                d = __dp4a(rw.y, cw.y, d);
                cutAcc += (float)d;
            }
        } else {
            for (int j = 0; j < 4; j++) {
                int eidx = 8 * j + qsel;
                int eid2 = (eidx < cnt) ? eidx : 0;
                int r  = __shfl_sync(0xffffffffu, r0, eid2);
                int cc = __shfl_sync(0xffffffffu, c0, eid2);
                if (eidx < cnt) {
                    uint2 rw = rows[r * 4 + quar];
                    uint2 cw = rows[cc * 4 + quar];
                    unsigned d = 0;
                    d = __dp4a(rw.x, cw.x, d);
                    d = __dp4a(rw.y, cw.y, d);
                    cutAcc += (float)d;
                }
            }
        }
    }
#pragma unroll
    for (int off = 16; off; off >>= 1)
        cutAcc += __shfl_xor_sync(0xffffffffu, cutAcc, off);
    if (lane == 0) atomicAdd(&g_cut, cutAcc);
}

// ---------------- Z = M @ W_proj + colsum(S) x b_proj  (grid (30,4), K-split, atomic) ----------------
__global__ __launch_bounds__(256) void k_gemmZ(const float* __restrict__ Wp,
                                               const float* __restrict__ bp) {
    __shared__ float sM[64];
    __shared__ float sP[4][IN_];
    const int c = blockIdx.x, kc = blockIdx.y, t = threadIdx.x;
    if (t < 64) sM[t] = g_M[c * IN_ + kc * 64 + t];
    __syncthreads();
    const int tg = t >> 6, tc = t & 63;
    const float4* W4 = (const float4*)Wp;
    float4 acc = make_float4(0.f, 0.f, 0.f, 0.f);
    const int kbase = kc * 64 + tg * 16;
#pragma unroll
    for (int k = 0; k < 16; k++) {
        float m = sM[tg * 16 + k];
        float4 wv = W4[(kbase + k) * 64 + tc];
        acc.x += m * wv.x; acc.y += m * wv.y;
        acc.z += m * wv.z; acc.w += m * wv.w;
    }
    ((float4*)sP[tg])[tc] = acc;
    __syncthreads();
    float r = sP[0][t] + sP[1][t] + sP[2][t] + sP[3][t];
    if (kc == 0) r += g_colsum[c] * bp[t];
    atomicAdd(&g_Z[c * IN_ + t], r);
}

// ---------------- Shapley layer: pre = (X + colsum(X)/30) @ W  (grid (30,4), atomic) ----------------
__global__ __launch_bounds__(256) void k_shap(const float* __restrict__ W, int layer,
                                              float* __restrict__ outZ) {
    __shared__ float sA[64];
    __shared__ float sP[4][IN_];
    const int c = blockIdx.x, kc = blockIdx.y, t = threadIdx.x;
    if (t < 64) {
        int d = kc * 64 + t;
        float tz = 0.f, own = 0.f;
        if (layer == 0) {
#pragma unroll
            for (int c2 = 0; c2 < C_; c2++) {
                float v = g_Z[c2 * IN_ + d];
                tz += v; if (c2 == c) own = v;
            }
            outZ[c * IN_ + d] = own;
        } else {
#pragma unroll
            for (int c2 = 0; c2 < C_; c2++) {
                float v = fmaxf(g_pre1[c2 * IN_ + d], 0.f);
                tz += v; if (c2 == c) own = v;
            }
        }
        sA[t] = own + tz * (1.f / 30.f);
    }
    __syncthreads();
    const int tg = t >> 6, tc = t & 63;
    const float4* W4 = (const float4*)W;
    float4 acc = make_float4(0.f, 0.f, 0.f, 0.f);
    const int kbase = kc * 64 + tg * 16;
#pragma unroll
    for (int k = 0; k < 16; k++) {
        float m = sA[tg * 16 + k];
        float4 wv = W4[(kbase + k) * 64 + tc];
        acc.x += m * wv.x; acc.y += m * wv.y;
        acc.z += m * wv.z; acc.w += m * wv.w;
    }
    ((float4*)sP[tg])[tc] = acc;
    __syncthreads();
    float r = sP[0][t] + sP[1][t] + sP[2][t] + sP[3][t];
    atomicAdd(((layer == 0) ? g_pre1 : g_pre2) + c * IN_ + t, r);
}

// ---------------- out = relu(pre2) @ W_out + b_out (grid (30,4), atomic) ----------------
__global__ __launch_bounds__(256) void k_out(const float* __restrict__ Wout,
                                             const float* __restrict__ bout,
                                             float* __restrict__ out) {
    __shared__ float sA[64];
    __shared__ float sP[4][OUT_];
    const int c = blockIdx.x, kc = blockIdx.y, t = threadIdx.x;
    if (t < 64) sA[t] = fmaxf(g_pre2[c * HID_ + kc * 64 + t], 0.f);
    __syncthreads();
    const int tg = t >> 6, tc = t & 63;
    float acc = 0.f;
    const int kbase = kc * 64 + tg * 16;
#pragma unroll
    for (int k = 0; k < 16; k++)
        acc += sA[tg * 16 + k] * Wout[(kbase + k) * OUT_ + tc];
    sP[tg][tc] = acc;
    __syncthreads();
    if (t < OUT_) {
        float r = sP[0][t] + sP[1][t] + sP[2][t] + sP[3][t];
        if (kc == 0) r += bout[t];
        atomicAdd(&out[c * OUT_ + t], r);
    }
}

// ---------------- scalar losses (vol = E exactly) ----------------
__global__ void k_loss(float* __restrict__ out, int E) {
    __shared__ float red[256];
    int t = threadIdx.x;
    float loc = 0.f;
    for (int i = t; i < C_ * C_; i += 256) {
        int a = i / C_, b = i - a * C_;
        float d = g_StS[a * 32 + b] - ((a == b) ? 1.f : 0.f);
        loc += d * d;
    }
    red[t] = loc;
    __syncthreads();
    for (int s = 128; s; s >>= 1) { if (t < s) red[t] += red[t + s]; __syncthreads(); }
    if (t == 0) {
        float cut = g_cut * (1.f / 65025.f);   // / 255^2
        out[1920] = -cut / ((float)E + 1e-9f); // mincut_loss (vol == E)
        out[1921] = sqrtf(red[0]);             // ortho_loss (Frobenius)
    }
}

// ---------------- launch: bind inputs BY SIZE ----------------
// Output layout (tuple order): out[30*64]=1920 | mincut 1 | ortho 1 | Z[30*256]=7680 | S[N*30]
extern "C" void kernel_launch(void* const* d_in, const int* in_sizes, int n_in,
                              void* d_out, int out_size) {
    const float *x = 0, *Wa = 0, *ba = 0, *Wp = 0, *bp = 0, *W1 = 0, *W2 = 0, *Wo = 0, *bo = 0;
    const int* ei = 0;
    const void* m65536[3] = {0, 0, 0}; int n65 = 0;
    const void* bigp[2] = {0, 0}; long long bigsz[2] = {0, 0}; int nbig = 0;

    for (int i = 0; i < n_in; i++) {
        long long s = in_sizes[i];
        const void* p = d_in[i];
        if (s == C_ * IN_)            Wa = (const float*)p;
        else if (s == C_)             ba = (const float*)p;
        else if (s == IN_)            bp = (const float*)p;
        else if (s == HID_ * OUT_)    Wo = (const float*)p;
        else if (s == OUT_)           bo = (const float*)p;
        else if (s == IN_ * HID_) { if (n65 < 3) m65536[n65++] = p; }
        else if (nbig < 2) { bigp[nbig] = p; bigsz[nbig] = s; nbig++; }
    }
    Wp = (const float*)m65536[0];
    W1 = (const float*)m65536[1];
    W2 = (const float*)m65536[2];

    int N, E;
    if (bigsz[0] >= bigsz[1]) {
        x = (const float*)bigp[0]; ei = (const int*)bigp[1];
        N = (int)(bigsz[0] / IN_); E = (int)(bigsz[1] / 2);
    } else {
        x = (const float*)bigp[1]; ei = (const int*)bigp[0];
        N = (int)(bigsz[1] / IN_); E = (int)(bigsz[0] / 2);
    }

    float* out = (float*)d_out;
    const int ZOFF = 1922;
    const int SOFF = 9602;

    k_zero<<<16, 256>>>(out);
    k_nop<<<1, 32>>>();              // aim: passA in the profiled 4th slot
    k_nop<<<1, 32>>>();
    k_passA<<<592, 256>>>(x, Wa, ba, out + SOFF, N);
    k_edges<<<592, 256>>>(ei, E);
    k_gemmZ<<<dim3(C_, 4), 256>>>(Wp, bp);
    k_shap<<<dim3(C_, 4), 256>>>(W1, 0, out + ZOFF);
    k_shap<<<dim3(C_, 4), 256>>>(W2, 1, out + ZOFF);
    k_out<<<dim3(C_, 4), 256>>>(Wo, bo, out);
    k_loss<<<1, 256>>>(out, E);
}

// round 17
// speedup vs baseline: 1.3402x; 1.0222x over previous
#include <cuda_runtime.h>
#include <cuda_bf16.h>
#include <math.h>

#define C_   30
#define IN_  256
#define HID_ 256
#define OUT_ 64
#define NMAX 100000

// ---------------- device scratch (no allocations allowed) ----------------
__device__ unsigned g_Sq[NMAX * 8];   // S row quantized: 32 uint8 = round(255*s), slots 30,31 = 0
__device__ float g_M[C_ * IN_];       // M = S^T x
__device__ float g_colsum[32];        // colsum(S)
__device__ float g_StS[C_ * 32];      // S^T S (padded cols)
__device__ float g_cut;               // scaled by 255^2
__device__ float g_Z[C_ * IN_];
__device__ float g_pre1[C_ * HID_];
__device__ float g_pre2[C_ * HID_];

// ---- packed f32x2 helpers (FFMA2 is PTX-only; ptxas never auto-fuses) ----
__device__ __forceinline__ void ffma2(unsigned long long& d, unsigned long long a,
                                      unsigned long long b) {
    asm("fma.rn.f32x2 %0, %1, %2, %3;" : "=l"(d) : "l"(a), "l"(b), "l"(d));
}
__device__ __forceinline__ unsigned long long pack2(float lo, float hi) {
    unsigned long long r;
    asm("mov.b64 %0, {%1, %2};" : "=l"(r) : "f"(lo), "f"(hi));
    return r;
}
__device__ __forceinline__ void unpack2(unsigned long long v, float& lo, float& hi) {
    asm("mov.b64 {%0, %1}, %2;" : "=f"(lo), "=f"(hi) : "l"(v));
}

// ---------------- profiler aimer: harness ncu captures the 4th launch ----------------
__global__ void k_nop() {}

// ---------------- zero accumulators + out region (must run every replay) ----------------
__global__ void k_zero(float* out) {
    const int i = blockIdx.x * 256 + threadIdx.x;
    const int stride = gridDim.x * 256;
    for (int j = i; j < C_ * IN_; j += stride) {
        g_M[j] = 0.f; g_Z[j] = 0.f; g_pre1[j] = 0.f; g_pre2[j] = 0.f;
    }
    for (int j = i; j < C_ * 32; j += stride) g_StS[j] = 0.f;
    for (int j = i; j < C_ * OUT_; j += stride) out[j] = 0.f;
    if (i < 32) g_colsum[i] = 0.f;
    if (i == 0) g_cut = 0.f;
}

// ---------------- fused node pass: S (softmax), M=S^T x, StS=S^T S, colsum ----------------
__global__ __launch_bounds__(256) void k_passA(
    const float* __restrict__ x, const float* __restrict__ Wa,
    const float* __restrict__ ba, float* __restrict__ outS, int N)
{
    __shared__ float sWt[15 * 512];  // pair-interleaved: [p][d][par] = Wa[d*30 + 2p+par]
    __shared__ float sS[128 * 32];   // per-tile S (padded to 32)
    __shared__ float sB[32];

    const int t = threadIdx.x;
    for (int i = t; i < 15 * 512; i += 256) {
        int p = i >> 9;
        int rem = i & 511;
        int d = rem >> 1, par = rem & 1;
        sWt[i] = Wa[d * C_ + 2 * p + par];
    }
    if (t < 32) sB[t] = (t < C_) ? ba[t] : 0.f;

    unsigned long long Macc2[15];
#pragma unroll
    for (int p = 0; p < 15; p++) Macc2[p] = 0ull;
    float a0 = 0.f, a1 = 0.f, a2 = 0.f, a3 = 0.f, colacc = 0.f;

    const int c1 = t >> 3;          // StS row owned (t<240 -> c1<30)
    const int q4 = (t & 7) * 4;     // StS col quad
    const int w = t >> 5, l = t & 31, lh = l & 15, half = l >> 4;

    const float4* x4 = (const float4*)x;
    float4* sS4 = (float4*)sS;

    __syncthreads();

    const int numTiles = (N + 127) >> 7;
    for (int tile = blockIdx.x; tile < numTiles; tile += gridDim.x) {
        const int base = tile << 7;
        const int nt = min(128, N - base);
        const int nl = w * 16 + lh;
        const int node = base + nl;

        // ---- phase 1: logits via FFMA2; lane covers d in [half*128, half*128+128)
        unsigned long long lg2[15];
#pragma unroll
        for (int p = 0; p < 15; p++) lg2[p] = 0ull;
        if (node < N) {
            const float4* xr = x4 + node * 64 + half * 32;
            const float* wbase = sWt + half * 256;
#pragma unroll 4
            for (int d4 = 0; d4 < 32; d4++) {
                float4 xv = xr[d4];
                unsigned long long xp0 = pack2(xv.x, xv.x);
                unsigned long long xp1 = pack2(xv.y, xv.y);
                unsigned long long xp2 = pack2(xv.z, xv.z);
                unsigned long long xp3 = pack2(xv.w, xv.w);
#pragma unroll
                for (int p = 0; p < 15; p++) {
                    const ulonglong2* wq =
                        (const ulonglong2*)(wbase + p * 512 + d4 * 8);
                    ulonglong2 w0 = wq[0];
                    ulonglong2 w1 = wq[1];
                    ffma2(lg2[p], xp0, w0.x);
                    ffma2(lg2[p], xp1, w0.y);
                    ffma2(lg2[p], xp2, w1.x);
                    ffma2(lg2[p], xp3, w1.y);
                }
            }
        }
        float lg[C_];
#pragma unroll
        for (int p = 0; p < 15; p++) unpack2(lg2[p], lg[2 * p], lg[2 * p + 1]);
#pragma unroll
        for (int c = 0; c < C_; c++) lg[c] += __shfl_xor_sync(0xffffffffu, lg[c], 16);
#pragma unroll
        for (int c = 0; c < C_; c++) lg[c] += sB[c];

        // softmax in registers
        float mx = lg[0];
#pragma unroll
        for (int c = 1; c < C_; c++) mx = fmaxf(mx, lg[c]);
        float sum = 0.f;
#pragma unroll
        for (int c = 0; c < C_; c++) { lg[c] = __expf(lg[c] - mx); sum += lg[c]; }
        float inv = 1.f / sum;
        float rs = 0.f;
#pragma unroll
        for (int c = 0; c < C_; c++) { lg[c] *= inv; rs += lg[c]; }

        if (half == 0) {
            float4* dst = sS4 + nl * 8;
            dst[0] = make_float4(lg[0],  lg[1],  lg[2],  lg[3]);
            dst[1] = make_float4(lg[4],  lg[5],  lg[6],  lg[7]);
            dst[2] = make_float4(lg[8],  lg[9],  lg[10], lg[11]);
            dst[3] = make_float4(lg[12], lg[13], lg[14], lg[15]);
            dst[4] = make_float4(lg[16], lg[17], lg[18], lg[19]);
            dst[5] = make_float4(lg[20], lg[21], lg[22], lg[23]);
            dst[6] = make_float4(lg[24], lg[25], lg[26], lg[27]);
            dst[7] = make_float4(lg[28], lg[29], rs, 0.f);
        }
        __syncthreads();

        // ---- phase 2: uint8-quantized S (32B rows, slots 30/31 = 0) + fp32 S to d_out
        for (int i = t; i < nt * 8; i += 256) {
            int nn = i >> 3, ww = i & 7;
            const float* sr = sS + nn * 32 + 4 * ww;
            unsigned q0 = __float2uint_rn(sr[0] * 255.f);
            unsigned q1 = __float2uint_rn(sr[1] * 255.f);
            unsigned q2 = 0, q3 = 0;
            if (ww < 7) {
                q2 = __float2uint_rn(sr[2] * 255.f);
                q3 = __float2uint_rn(sr[3] * 255.f);
            }
            g_Sq[base * 8 + i] = q0 | (q1 << 8) | (q2 << 16) | (q3 << 24);
        }
        for (int i = t; i < nt * 30; i += 256) {
            int nn = i / 30;
            int cc = i - nn * 30;
            outS[base * 30 + i] = sS[nn * 32 + cc];
        }

        // ---- phase 3: M += S^T x via FFMA2, StS += S^T S, colsum (exact fp32)
        for (int i = 0; i < nt; i++) {
            float xv = x[(base + i) * 256 + t];
            unsigned long long xp = pack2(xv, xv);
            const ulonglong2* sr = (const ulonglong2*)(sS + i * 32);
            ulonglong2 r0 = sr[0], r1 = sr[1], r2 = sr[2], r3 = sr[3];
            ffma2(Macc2[0], xp, r0.x);  ffma2(Macc2[1], xp, r0.y);
            ffma2(Macc2[2], xp, r1.x);  ffma2(Macc2[3], xp, r1.y);
            ffma2(Macc2[4], xp, r2.x);  ffma2(Macc2[5], xp, r2.y);
            ffma2(Macc2[6], xp, r3.x);  ffma2(Macc2[7], xp, r3.y);
            ulonglong2 r4 = sr[4], r5 = sr[5], r6 = sr[6];
            ffma2(Macc2[8],  xp, r4.x); ffma2(Macc2[9],  xp, r4.y);
            ffma2(Macc2[10], xp, r5.x); ffma2(Macc2[11], xp, r5.y);
            ffma2(Macc2[12], xp, r6.x); ffma2(Macc2[13], xp, r6.y);
            ffma2(Macc2[14], xp, ((const unsigned long long*)(sS + i * 32))[14]);
            if (t < 240) {
                float sc = sS[i * 32 + c1];
                float4 sq = sS4[i * 8 + (q4 >> 2)];
                a0 += sc * sq.x; a1 += sc * sq.y;
                a2 += sc * sq.z; a3 += sc * sq.w;
            }
            if (t < 32) colacc += sS[i * 32 + t];
        }
        __syncthreads();
    }

#pragma unroll
    for (int p = 0; p < 15; p++) {
        float lo, hi;
        unpack2(Macc2[p], lo, hi);
        atomicAdd(&g_M[(2 * p) * IN_ + t], lo);
        atomicAdd(&g_M[(2 * p + 1) * IN_ + t], hi);
    }
    if (t < 240) {
        atomicAdd(&g_StS[c1 * 32 + q4 + 0], a0);
        atomicAdd(&g_StS[c1 * 32 + q4 + 1], a1);
        atomicAdd(&g_StS[c1 * 32 + q4 + 2], a2);
        atomicAdd(&g_StS[c1 * 32 + q4 + 3], a3);
    }
    if (t < 30) atomicAdd(&g_colsum[t], colacc);
}

// ---------------- edge pass: uint8 + dp4a, 8 edges/warp-iter, 8B loads/lane ----------------
__global__ __launch_bounds__(256) void k_edges(const int* __restrict__ ei, int E) {
    __shared__ int s_i64;
    if (threadIdx.x == 0) {
        int nz = 0;
#pragma unroll
        for (int j = 1; j < 64; j += 2) nz |= ei[j];  // int64 high words are 0
        s_i64 = (nz == 0);
    }
    __syncthreads();
    const bool i64 = (s_i64 != 0);

    const int lane = threadIdx.x & 31;
    const int gw = (blockIdx.x * 256 + threadIdx.x) >> 5;
    const int nwarp = gridDim.x * 8;
    const int quar = lane & 3;      // uint2 (8 bytes) within 32B row
    const int qsel = lane >> 2;     // which of 8 edges this lane-quad handles
    const uint2* rows = reinterpret_cast<const uint2*>(g_Sq);
    float cutAcc = 0.f;

    for (int b = gw * 32; b < E; b += nwarp * 32) {
        int e = b + lane;
        int r0 = 0, c0 = 0;
        if (e < E) {
            if (i64) { r0 = ei[2 * e]; c0 = ei[2 * E + 2 * e]; }
            else     { r0 = ei[e];     c0 = ei[E + e]; }
        }
        int cnt = min(32, E - b);
        if (cnt == 32) {
#pragma unroll
            for (int j = 0; j < 4; j++) {
                int eidx = 8 * j + qsel;
                int r  = __shfl_sync(0xffffffffu, r0, eidx);
                int cc = __shfl_sync(0xffffffffu, c0, eidx);
                uint2 rw = rows[r * 4 + quar];
                uint2 cw = rows[cc * 4 + quar];
                unsigned d = 0;
                d = __dp4a(rw.x, cw.x, d);
                d = __dp4a(rw.y, cw.y, d);
                cutAcc += (float)d;
            }
        } else {
            for (int j = 0; j < 4; j++) {
                int eidx = 8 * j + qsel;
                int eid2 = (eidx < cnt) ? eidx : 0;
                int r  = __shfl_sync(0xffffffffu, r0, eid2);
                int cc = __shfl_sync(0xffffffffu, c0, eid2);
                if (eidx < cnt) {
                    uint2 rw = rows[r * 4 + quar];
                    uint2 cw = rows[cc * 4 + quar];
                    unsigned d = 0;
                    d = __dp4a(rw.x, cw.x, d);
                    d = __dp4a(rw.y, cw.y, d);
                    cutAcc += (float)d;
                }
            }
        }
    }
#pragma unroll
    for (int off = 16; off; off >>= 1)
        cutAcc += __shfl_xor_sync(0xffffffffu, cutAcc, off);
    if (lane == 0) atomicAdd(&g_cut, cutAcc);
}

// ---------------- Z = M @ W_proj + colsum(S) x b_proj  (grid (30,4), K-split, atomic) ----------------
__global__ __launch_bounds__(256) void k_gemmZ(const float* __restrict__ Wp,
                                               const float* __restrict__ bp) {
    __shared__ float sM[64];
    __shared__ float sP[4][IN_];
    const int c = blockIdx.x, kc = blockIdx.y, t = threadIdx.x;
    if (t < 64) sM[t] = g_M[c * IN_ + kc * 64 + t];
    __syncthreads();
    const int tg = t >> 6, tc = t & 63;
    const float4* W4 = (const float4*)Wp;
    float4 acc = make_float4(0.f, 0.f, 0.f, 0.f);
    const int kbase = kc * 64 + tg * 16;
#pragma unroll
    for (int k = 0; k < 16; k++) {
        float m = sM[tg * 16 + k];
        float4 wv = W4[(kbase + k) * 64 + tc];
        acc.x += m * wv.x; acc.y += m * wv.y;
        acc.z += m * wv.z; acc.w += m * wv.w;
    }
    ((float4*)sP[tg])[tc] = acc;
    __syncthreads();
    float r = sP[0][t] + sP[1][t] + sP[2][t] + sP[3][t];
    if (kc == 0) r += g_colsum[c] * bp[t];
    atomicAdd(&g_Z[c * IN_ + t], r);
}

// ---------------- Shapley layer: pre = (X + colsum(X)/30) @ W  (grid (30,4), atomic) ----------------
__global__ __launch_bounds__(256) void k_shap(const float* __restrict__ W, int layer,
                                              float* __restrict__ outZ) {
    __shared__ float sA[64];
    __shared__ float sP[4][IN_];
    const int c = blockIdx.x, kc = blockIdx.y, t = threadIdx.x;
    if (t < 64) {
        int d = kc * 64 + t;
        float tz = 0.f, own = 0.f;
        if (layer == 0) {
#pragma unroll
            for (int c2 = 0; c2 < C_; c2++) {
                float v = g_Z[c2 * IN_ + d];
                tz += v; if (c2 == c) own = v;
            }
            outZ[c * IN_ + d] = own;
        } else {
#pragma unroll
            for (int c2 = 0; c2 < C_; c2++) {
                float v = fmaxf(g_pre1[c2 * IN_ + d], 0.f);
                tz += v; if (c2 == c) own = v;
            }
        }
        sA[t] = own + tz * (1.f / 30.f);
    }
    __syncthreads();
    const int tg = t >> 6, tc = t & 63;
    const float4* W4 = (const float4*)W;
    float4 acc = make_float4(0.f, 0.f, 0.f, 0.f);
    const int kbase = kc * 64 + tg * 16;
#pragma unroll
    for (int k = 0; k < 16; k++) {
        float m = sA[tg * 16 + k];
        float4 wv = W4[(kbase + k) * 64 + tc];
        acc.x += m * wv.x; acc.y += m * wv.y;
        acc.z += m * wv.z; acc.w += m * wv.w;
    }
    ((float4*)sP[tg])[tc] = acc;
    __syncthreads();
    float r = sP[0][t] + sP[1][t] + sP[2][t] + sP[3][t];
    atomicAdd(((layer == 0) ? g_pre1 : g_pre2) + c * IN_ + t, r);
}

// ---------------- out = relu(pre2) @ W_out + b_out (grid (30,4), atomic) ----------------
__global__ __launch_bounds__(256) void k_out(const float* __restrict__ Wout,
                                             const float* __restrict__ bout,
                                             float* __restrict__ out) {
    __shared__ float sA[64];
    __shared__ float sP[4][OUT_];
    const int c = blockIdx.x, kc = blockIdx.y, t = threadIdx.x;
    if (t < 64) sA[t] = fmaxf(g_pre2[c * HID_ + kc * 64 + t], 0.f);
    __syncthreads();
    const int tg = t >> 6, tc = t & 63;
    float acc = 0.f;
    const int kbase = kc * 64 + tg * 16;
#pragma unroll
    for (int k = 0; k < 16; k++)
        acc += sA[tg * 16 + k] * Wout[(kbase + k) * OUT_ + tc];
    sP[tg][tc] = acc;
    __syncthreads();
    if (t < OUT_) {
        float r = sP[0][t] + sP[1][t] + sP[2][t] + sP[3][t];
        if (kc == 0) r += bout[t];
        atomicAdd(&out[c * OUT_ + t], r);
    }
}

// ---------------- scalar losses (vol = E exactly) ----------------
__global__ void k_loss(float* __restrict__ out, int E) {
    __shared__ float red[256];
    int t = threadIdx.x;
    float loc = 0.f;
    for (int i = t; i < C_ * C_; i += 256) {
        int a = i / C_, b = i - a * C_;
        float d = g_StS[a * 32 + b] - ((a == b) ? 1.f : 0.f);
        loc += d * d;
    }
    red[t] = loc;
    __syncthreads();
    for (int s = 128; s; s >>= 1) { if (t < s) red[t] += red[t + s]; __syncthreads(); }
    if (t == 0) {
        float cut = g_cut * (1.f / 65025.f);   // / 255^2
        out[1920] = -cut / ((float)E + 1e-9f); // mincut_loss (vol == E)
        out[1921] = sqrtf(red[0]);             // ortho_loss (Frobenius)
    }
}

// ---------------- launch: bind inputs BY SIZE; edges forked onto a parallel branch ----------------
// Output layout (tuple order): out[30*64]=1920 | mincut 1 | ortho 1 | Z[30*256]=7680 | S[N*30]
extern "C" void kernel_launch(void* const* d_in, const int* in_sizes, int n_in,
                              void* d_out, int out_size) {
    const float *x = 0, *Wa = 0, *ba = 0, *Wp = 0, *bp = 0, *W1 = 0, *W2 = 0, *Wo = 0, *bo = 0;
    const int* ei = 0;
    const void* m65536[3] = {0, 0, 0}; int n65 = 0;
    const void* bigp[2] = {0, 0}; long long bigsz[2] = {0, 0}; int nbig = 0;

    for (int i = 0; i < n_in; i++) {
        long long s = in_sizes[i];
        const void* p = d_in[i];
        if (s == C_ * IN_)            Wa = (const float*)p;
        else if (s == C_)             ba = (const float*)p;
        else if (s == IN_)            bp = (const float*)p;
        else if (s == HID_ * OUT_)    Wo = (const float*)p;
        else if (s == OUT_)           bo = (const float*)p;
        else if (s == IN_ * HID_) { if (n65 < 3) m65536[n65++] = p; }
        else if (nbig < 2) { bigp[nbig] = p; bigsz[nbig] = s; nbig++; }
    }
    Wp = (const float*)m65536[0];
    W1 = (const float*)m65536[1];
    W2 = (const float*)m65536[2];

    int N, E;
    if (bigsz[0] >= bigsz[1]) {
        x = (const float*)bigp[0]; ei = (const int*)bigp[1];
        N = (int)(bigsz[0] / IN_); E = (int)(bigsz[1] / 2);
    } else {
        x = (const float*)bigp[1]; ei = (const int*)bigp[0];
        N = (int)(bigsz[1] / IN_); E = (int)(bigsz[0] / 2);
    }

    float* out = (float*)d_out;
    const int ZOFF = 1922;
    const int SOFF = 9602;

    // host-side stream/event objects (created once; not device memory)
    static cudaStream_t s2 = 0;
    static cudaEvent_t evFork = 0, evJoin = 0;
    if (!s2) {
        cudaStreamCreateWithFlags(&s2, cudaStreamNonBlocking);
        cudaEventCreateWithFlags(&evFork, cudaEventDisableTiming);
        cudaEventCreateWithFlags(&evJoin, cudaEventDisableTiming);
    }

    k_zero<<<16, 256>>>(out);
    k_nop<<<1, 32>>>();              // aim: passA in the profiled 4th slot
    k_nop<<<1, 32>>>();
    k_passA<<<592, 256>>>(x, Wa, ba, out + SOFF, N);

    // fork: edge pass runs concurrently with the tail GEMM chain
    cudaEventRecord(evFork, 0);
    cudaStreamWaitEvent(s2, evFork, 0);
    k_edges<<<592, 256, 0, s2>>>(ei, E);
    cudaEventRecord(evJoin, s2);

    k_gemmZ<<<dim3(C_, 4), 256>>>(Wp, bp);
    k_shap<<<dim3(C_, 4), 256>>>(W1, 0, out + ZOFF);
    k_shap<<<dim3(C_, 4), 256>>>(W2, 1, out + ZOFF);
    k_out<<<dim3(C_, 4), 256>>>(Wo, bo, out);

    // join: losses need both branches
    cudaStreamWaitEvent(0, evJoin, 0);
    k_loss<<<1, 256>>>(out, E);
}